// round 6
// baseline (speedup 1.0000x reference)
#include <cuda_runtime.h>
#include <cuda_fp16.h>
#include <cstdint>

#define T_   128
#define B_   64
#define E_   300
#define H_   2048
#define G4   8192
#define TB   8192
#define KP   320
#define KCAT 960

// step-kernel config
#define NCTA   128
#define NT     64                 // gate rows per CTA
#define JT     16                 // hidden units per CTA
#define STAGES 3
#define A_BYTES 18432             // 128 rows x 144B
#define B_BYTES 9216              // 64 rows x 144B
#define STAGE_BYTES (A_BYTES + B_BYTES)   // 27648
#define DYN_SMEM (STAGES * STAGE_BYTES)   // 82944

// ---------------- scratch ----------------
__device__ __align__(256) __half g_Acat[(size_t)TB * KCAT];
__device__ __align__(256) __half g_Bcat[(size_t)G4 * KCAT];
__device__ __align__(256) __half g_Whh16[(size_t)G4 * H_];   // gate-interleaved rows
__device__ __align__(256) float  g_Xg[(size_t)TB * G4];      // [t*B+b][np] np=4j+g
__device__ __align__(256) float  g_bias[G4];
__device__ __align__(256) float  g_c[128 * H_];              // cell state
__device__ __align__(256) __half g_h16[128 * H_];            // hidden state

// ---------------- helpers ----------------
__device__ __forceinline__ uint32_t smemAddr(const void* p) {
    return (uint32_t)__cvta_generic_to_shared(p);
}
__device__ __forceinline__ void ldsm4(uint32_t r[4], uint32_t addr) {
    asm volatile("ldmatrix.sync.aligned.m8n8.x4.shared.b16 {%0,%1,%2,%3}, [%4];\n"
                 : "=r"(r[0]), "=r"(r[1]), "=r"(r[2]), "=r"(r[3]) : "r"(addr));
}
__device__ __forceinline__ void mma16816(float* c, const uint32_t* a, const uint32_t* b) {
    asm volatile("mma.sync.aligned.m16n8k16.row.col.f32.f16.f16.f32 "
                 "{%0,%1,%2,%3}, {%4,%5,%6,%7}, {%8,%9}, {%0,%1,%2,%3};\n"
                 : "+f"(c[0]), "+f"(c[1]), "+f"(c[2]), "+f"(c[3])
                 : "r"(a[0]), "r"(a[1]), "r"(a[2]), "r"(a[3]), "r"(b[0]), "r"(b[1]));
}
#define CP16(dst, src) asm volatile("cp.async.cg.shared.global [%0], [%1], 16;\n" :: "r"(dst), "l"(src))
#define CP_COMMIT()    asm volatile("cp.async.commit_group;\n" ::: "memory")
#define CP_WAIT(N)     asm volatile("cp.async.wait_group %0;\n" :: "n"(N) : "memory")

__device__ __forceinline__ float sigm(float x) { return 1.f / (1.f + __expf(-x)); }
__device__ __forceinline__ float tanh_f(float x) { return 2.f / (1.f + __expf(-2.f * x)) - 1.f; }

// ---------------- prep kernels ----------------
__global__ void prep_whh(const float* __restrict__ W) {
    int i = blockIdx.x * blockDim.x + threadIdx.x;
    if (i >= G4 * H_) return;
    int n = i >> 11, k = i & (H_ - 1);
    int np = ((n & (H_ - 1)) << 2) | (n >> 11);     // gate-interleaved row
    g_Whh16[(size_t)np * H_ + k] = __float2half(W[i]);
}
__global__ void prep_wih(const float* __restrict__ W) {
    int i = blockIdx.x * blockDim.x + threadIdx.x;
    if (i >= G4 * KP) return;
    int n = i / KP, c = i % KP;
    int np = ((n & (H_ - 1)) << 2) | (n >> 11);
    float w = (c < E_) ? W[n * E_ + c] : 0.f;
    __half hi = __float2half(w);
    __half lo = __float2half(w - __half2float(hi));
    g_Bcat[(size_t)np * KCAT + c]          = hi;
    g_Bcat[(size_t)np * KCAT + KP + c]     = lo;
    g_Bcat[(size_t)np * KCAT + 2 * KP + c] = hi;
}
__global__ void prep_bias(const float* __restrict__ a, const float* __restrict__ b) {
    int i = blockIdx.x * blockDim.x + threadIdx.x;
    if (i < G4) g_bias[i] = a[i] + b[i];
}
__global__ void prep_x(const int* __restrict__ tokens, const float* __restrict__ embed) {
    int i = blockIdx.x * blockDim.x + threadIdx.x;
    if (i >= TB * KP) return;
    int row = i / KP, c = i % KP;
    int tok = tokens[row];
    float v = (c < E_) ? embed[(size_t)tok * E_ + c] : 0.f;
    __half hi = __float2half(v);
    __half lo = __float2half(v - __half2float(hi));
    g_Acat[(size_t)row * KCAT + c]          = hi;
    g_Acat[(size_t)row * KCAT + KP + c]     = hi;
    g_Acat[(size_t)row * KCAT + 2 * KP + c] = lo;
}
__global__ void init_state() {
    int i = blockIdx.x * blockDim.x + threadIdx.x;
    if (i < 128 * H_) { g_c[i] = 0.f; g_h16[i] = __float2half(0.f); }
}

// ---------------- Xg GEMM (C[M,N]=A@B^T, tile 128x64, runs once) ----------------
__global__ __launch_bounds__(256) void gemm_kernel(
    const __half* __restrict__ A, const __half* __restrict__ B, float* __restrict__ C,
    int lda, int ldb, int ldc, int K)
{
    __shared__ __half As[128][72];
    __shared__ __half Bs[64][72];
    int tid = threadIdx.x, lane = tid & 31, warp = tid >> 5;
    int wm = warp & 3, wn = warp >> 2;
    int m0 = blockIdx.y * 128, n0 = blockIdx.x * 64;

    float acc[2][4][4];
#pragma unroll
    for (int mi = 0; mi < 2; mi++)
#pragma unroll
        for (int ni = 0; ni < 4; ni++)
#pragma unroll
            for (int q = 0; q < 4; q++) acc[mi][ni][q] = 0.f;

    uint32_t asB = smemAddr(As), bsB = smemAddr(Bs);
    uint32_t aRowByte = (uint32_t)(wm * 32 + (lane & 15)) * 144;
    uint32_t aColByte = (uint32_t)((lane >> 4) << 3) * 2;
    uint32_t bRowByte = (uint32_t)(wn * 32 + ((lane >> 4) & 1) * 8 + (lane & 7)) * 144;
    uint32_t bColByte = (uint32_t)(((lane >> 3) & 1) << 3) * 2;

    for (int k0 = 0; k0 < K; k0 += 64) {
#pragma unroll
        for (int i = 0; i < 4; i++) {
            int v = tid + i * 256; int r = v >> 3, cc = (v & 7) << 3;
            *(uint4*)&As[r][cc] = *(const uint4*)&A[(size_t)(m0 + r) * lda + k0 + cc];
        }
#pragma unroll
        for (int i = 0; i < 2; i++) {
            int v = tid + i * 256; int r = v >> 3, cc = (v & 7) << 3;
            *(uint4*)&Bs[r][cc] = *(const uint4*)&B[(size_t)(n0 + r) * ldb + k0 + cc];
        }
        __syncthreads();
#pragma unroll
        for (int ks = 0; ks < 4; ks++) {
            uint32_t a[2][4], b[2][4];
            uint32_t ka = (uint32_t)ks * 32;
            ldsm4(a[0], asB + aRowByte + ka + aColByte);
            ldsm4(a[1], asB + aRowByte + 16u * 144 + ka + aColByte);
            ldsm4(b[0], bsB + bRowByte + ka + bColByte);
            ldsm4(b[1], bsB + bRowByte + 16u * 144 + ka + bColByte);
#pragma unroll
            for (int mi = 0; mi < 2; mi++)
#pragma unroll
                for (int ni = 0; ni < 4; ni++)
                    mma16816(acc[mi][ni], a[mi], &b[ni >> 1][(ni & 1) * 2]);
        }
        __syncthreads();
    }
#pragma unroll
    for (int mi = 0; mi < 2; mi++) {
        int row = m0 + wm * 32 + mi * 16 + (lane >> 2);
#pragma unroll
        for (int ni = 0; ni < 4; ni++) {
            int col = n0 + wn * 32 + ni * 8 + ((lane & 3) << 1);
            float* cp = C + (size_t)row * ldc + col;
            cp[0] = acc[mi][ni][0]; cp[1] = acc[mi][ni][1];
            cp += (size_t)ldc * 8;
            cp[0] = acc[mi][ni][2]; cp[1] = acc[mi][ni][3];
        }
    }
}

// ---------------- fused LSTM step kernel (one launch per timestep) ----------------
// grid 128 CTAs x 256 thr. CTA owns gate rows n0..n0+63 = hidden units j0..j0+15.
// gates = h @ Whh_slice^T (3-stage cp.async + mma.sync), then fused pointwise.
__global__ __launch_bounds__(256, 1) void lstm_step(
    int s, const int* __restrict__ lens, float* __restrict__ out)
{
    extern __shared__ char dsm[];
    __shared__ float Cs[128][68];
    __shared__ float sBias[NT];

    const int tid = threadIdx.x, lane = tid & 31, warp = tid >> 5;
    const int wm = warp & 3, wn = warp >> 2;
    const int cta = blockIdx.x;
    const int n0 = cta * NT;
    const int j0 = cta * JT;

    const uint32_t dynB = smemAddr(dsm);

    if (tid < NT) sBias[tid] = g_bias[(tid & 3) * H_ + j0 + (tid >> 2)];

    // loader offsets
    uint32_t aDst[4]; const __half* aSrc[4];
#pragma unroll
    for (int i = 0; i < 4; i++) {
        int v = tid + i * 256, r = v >> 3, sg = v & 7;
        aDst[i] = (uint32_t)(r * 144 + sg * 16);
        aSrc[i] = g_h16 + (size_t)r * H_ + sg * 8;
    }
    uint32_t bDst[2]; const __half* bSrc[2];
#pragma unroll
    for (int i = 0; i < 2; i++) {
        int v = tid + i * 256, r = v >> 3, sg = v & 7;
        bDst[i] = (uint32_t)(r * 144 + sg * 16);
        bSrc[i] = g_Whh16 + (size_t)(n0 + r) * H_ + sg * 8;
    }

    const uint32_t aRowByte = (uint32_t)(wm * 32 + (lane & 15)) * 144;
    const uint32_t aColByte = (uint32_t)((lane >> 4) << 3) * 2;
    const uint32_t bRowByte = (uint32_t)(wn * 32 + ((lane >> 4) & 1) * 8 + (lane & 7)) * 144;
    const uint32_t bColByte = (uint32_t)(((lane >> 3) & 1) << 3) * 2;

    float acc[2][4][4];
#pragma unroll
    for (int mi = 0; mi < 2; mi++)
#pragma unroll
        for (int ni = 0; ni < 4; ni++)
#pragma unroll
            for (int q = 0; q < 4; q++) acc[mi][ni][q] = 0.f;

    // prologue: stages 0,1 <- chunks 0,1
#pragma unroll
    for (int p = 0; p < 2; p++) {
        uint32_t aB = dynB + p * STAGE_BYTES, bB = aB + A_BYTES;
#pragma unroll
        for (int i = 0; i < 4; i++) CP16(aB + aDst[i], aSrc[i] + p * 64);
#pragma unroll
        for (int i = 0; i < 2; i++) CP16(bB + bDst[i], bSrc[i] + p * 64);
        CP_COMMIT();
    }

    for (int ck = 0; ck < 32; ck++) {
        if (ck < 30) CP_WAIT(1); else CP_WAIT(0);
        __syncthreads();
        if (ck + 2 < 32) {
            int st = (ck + 2) % STAGES;
            uint32_t aB = dynB + st * STAGE_BYTES, bB = aB + A_BYTES;
#pragma unroll
            for (int i = 0; i < 4; i++) CP16(aB + aDst[i], aSrc[i] + (ck + 2) * 64);
#pragma unroll
            for (int i = 0; i < 2; i++) CP16(bB + bDst[i], bSrc[i] + (ck + 2) * 64);
            CP_COMMIT();
        }
        uint32_t asB = dynB + (ck % STAGES) * STAGE_BYTES;
        uint32_t bsB = asB + A_BYTES;
#pragma unroll
        for (int ks = 0; ks < 4; ks++) {
            uint32_t a[2][4], b[2][4];
            uint32_t ka = (uint32_t)ks * 32;
            ldsm4(a[0], asB + aRowByte + ka + aColByte);
            ldsm4(a[1], asB + aRowByte + 16u * 144 + ka + aColByte);
            ldsm4(b[0], bsB + bRowByte + ka + bColByte);
            ldsm4(b[1], bsB + bRowByte + 16u * 144 + ka + bColByte);
#pragma unroll
            for (int mi = 0; mi < 2; mi++)
#pragma unroll
                for (int ni = 0; ni < 4; ni++)
                    mma16816(acc[mi][ni], a[mi], &b[ni >> 1][(ni & 1) * 2]);
        }
    }

    // acc -> smem C
    __syncthreads();
#pragma unroll
    for (int mi = 0; mi < 2; mi++) {
        int row = wm * 32 + mi * 16 + (lane >> 2);
#pragma unroll
        for (int ni = 0; ni < 4; ni++) {
            int col = wn * 32 + ni * 8 + ((lane & 3) << 1);
            Cs[row][col]     = acc[mi][ni][0];
            Cs[row][col + 1] = acc[mi][ni][1];
            Cs[row + 8][col]     = acc[mi][ni][2];
            Cs[row + 8][col + 1] = acc[mi][ni][3];
        }
    }
    __syncthreads();

    // -------- fused pointwise: thread -> 8 hidden units of batch row pm --------
    const int pm = tid & 127;
    const int ph = tid >> 7;
    const int pb = pm & 63;
    const int t = (pm < 64) ? s : (T_ - 1 - s);
    const int myLen = lens[pb];
    const float* xg = g_Xg + (size_t)(t * B_ + pb) * G4 + 4 * (j0 + ph * 8);
    float* cptr = g_c + (size_t)pm * H_ + j0 + ph * 8;
    float4 c0 = *(const float4*)(cptr);
    float4 c1 = *(const float4*)(cptr + 4);
    float cst[8] = {c0.x, c0.y, c0.z, c0.w, c1.x, c1.y, c1.z, c1.w};

    __half hv8[8];
#pragma unroll
    for (int q = 0; q < 8; q++) {
        int jl = ph * 8 + q, nl = 4 * jl;
        float4 z  = *(const float4*)&Cs[pm][nl];
        float4 x4 = *(const float4*)(xg + 4 * q);
        float zi = z.x + x4.x + sBias[nl + 0];
        float zf = z.y + x4.y + sBias[nl + 1];
        float zg = z.z + x4.z + sBias[nl + 2];
        float zo = z.w + x4.w + sBias[nl + 3];
        float cv = sigm(zf) * cst[q] + sigm(zi) * tanh_f(zg);
        float hv = sigm(zo) * tanh_f(cv);
        cst[q] = cv;
        hv8[q] = __float2half(hv);
        if (pm < 64) {
            if (myLen == s + 1) out[(size_t)pb * (2 * H_) + j0 + jl] = hv;
        } else if (s == T_ - 1) {
            out[(size_t)pb * (2 * H_) + H_ + j0 + jl] = hv;
        }
    }
    *(float4*)(cptr)     = make_float4(cst[0], cst[1], cst[2], cst[3]);
    *(float4*)(cptr + 4) = make_float4(cst[4], cst[5], cst[6], cst[7]);
    *(uint4*)&g_h16[(size_t)pm * H_ + j0 + ph * 8] = *(uint4*)hv8;
}

// ---------------- launch ----------------
extern "C" void kernel_launch(void* const* d_in, const int* in_sizes, int n_in,
                              void* d_out, int out_size)
{
    (void)in_sizes; (void)n_in; (void)out_size;
    const int*   tokens = (const int*)  d_in[0];
    const int*   lens   = (const int*)  d_in[1];
    const float* embed  = (const float*)d_in[2];
    const float* W_ih   = (const float*)d_in[3];
    const float* W_hh   = (const float*)d_in[4];
    const float* b_ih   = (const float*)d_in[5];
    const float* b_hh   = (const float*)d_in[6];
    float* out = (float*)d_out;

    cudaFuncSetAttribute(lstm_step,
                         cudaFuncAttributeMaxDynamicSharedMemorySize, DYN_SMEM);

    void *pA, *pB, *pXg;
    cudaGetSymbolAddress(&pA, g_Acat);
    cudaGetSymbolAddress(&pB, g_Bcat);
    cudaGetSymbolAddress(&pXg, g_Xg);

    prep_whh <<<(G4 * H_ + 255) / 256, 256>>>(W_hh);
    prep_wih <<<(G4 * KP + 255) / 256, 256>>>(W_ih);
    prep_bias<<<(G4 + 255) / 256, 256>>>(b_ih, b_hh);
    prep_x   <<<(TB * KP + 255) / 256, 256>>>(tokens, embed);
    init_state<<<(128 * H_ + 255) / 256, 256>>>();

    gemm_kernel<<<dim3(G4 / 64, TB / 128), 256>>>(
        (const __half*)pA, (const __half*)pB, (float*)pXg, KCAT, KCAT, G4, KCAT);

    for (int s = 0; s < T_; s++)
        lstm_step<<<NCTA, 256, DYN_SMEM>>>(s, lens, out);
}

// round 7
// speedup vs baseline: 1.0327x; 1.0327x over previous
#include <cuda_runtime.h>
#include <cuda_fp16.h>
#include <cstdint>

#define T_   128
#define B_   64
#define E_   300
#define H_   2048
#define G4   8192
#define TB   8192
#define KP   320
#define KCAT 960

// step-kernel config
#define NCTA   128
#define NT     64                 // gate rows per CTA
#define JT     16                 // hidden units per CTA
#define STAGES 4
#define A_BYTES 18432             // 128 rows x 144B
#define B_BYTES 9216              // 64 rows x 144B
#define STAGE_BYTES (A_BYTES + B_BYTES)     // 27648
#define XG_OFF  (STAGES * STAGE_BYTES)      // 110592
#define XG_BYTES 32768                      // 128 rows x 256B
#define DYN_SMEM (XG_OFF + XG_BYTES)        // 143360

// ---------------- scratch ----------------
__device__ __align__(256) __half g_Acat[(size_t)TB * KCAT];
__device__ __align__(256) __half g_Bcat[(size_t)G4 * KCAT];
__device__ __align__(256) __half g_Whh16[(size_t)G4 * H_];   // gate-interleaved rows
__device__ __align__(256) float  g_Xg[(size_t)TB * G4];      // [t*B+b][np] np=4j+g
__device__ __align__(256) float  g_bias[G4];
__device__ __align__(256) float  g_c[128 * H_];              // cell state
__device__ __align__(256) __half g_h16[128 * H_];            // hidden state

// ---------------- helpers ----------------
__device__ __forceinline__ uint32_t smemAddr(const void* p) {
    return (uint32_t)__cvta_generic_to_shared(p);
}
__device__ __forceinline__ void ldsm4(uint32_t r[4], uint32_t addr) {
    asm volatile("ldmatrix.sync.aligned.m8n8.x4.shared.b16 {%0,%1,%2,%3}, [%4];\n"
                 : "=r"(r[0]), "=r"(r[1]), "=r"(r[2]), "=r"(r[3]) : "r"(addr));
}
__device__ __forceinline__ void mma16816(float* c, const uint32_t* a, const uint32_t* b) {
    asm volatile("mma.sync.aligned.m16n8k16.row.col.f32.f16.f16.f32 "
                 "{%0,%1,%2,%3}, {%4,%5,%6,%7}, {%8,%9}, {%0,%1,%2,%3};\n"
                 : "+f"(c[0]), "+f"(c[1]), "+f"(c[2]), "+f"(c[3])
                 : "r"(a[0]), "r"(a[1]), "r"(a[2]), "r"(a[3]), "r"(b[0]), "r"(b[1]));
}
#define CP16(dst, src) asm volatile("cp.async.cg.shared.global [%0], [%1], 16;\n" :: "r"(dst), "l"(src))
#define CP_COMMIT()    asm volatile("cp.async.commit_group;\n" ::: "memory")
#define CP_WAIT(N)     asm volatile("cp.async.wait_group %0;\n" :: "n"(N) : "memory")

__device__ __forceinline__ float sigm(float x) { return 1.f / (1.f + __expf(-x)); }
__device__ __forceinline__ float tanh_f(float x) { return 2.f / (1.f + __expf(-2.f * x)) - 1.f; }

// ---------------- merged prep kernel (block-range dispatch) ----------------
#define NB_WHH  65536     // G4*H/256
#define NB_WIH  10240     // G4*KP/256
#define NB_X    10240     // TB*KP/256
#define NB_MISC 1056      // 1024 (state) + 32 (bias)
__global__ void prep_all(const int* __restrict__ tokens, const float* __restrict__ embed,
                         const float* __restrict__ W_ih, const float* __restrict__ W_hh,
                         const float* __restrict__ b_ih, const float* __restrict__ b_hh)
{
    int blk = blockIdx.x;
    if (blk < NB_WHH) {
        int i = blk * 256 + threadIdx.x;
        int n = i >> 11, k = i & (H_ - 1);
        int np = ((n & (H_ - 1)) << 2) | (n >> 11);
        g_Whh16[(size_t)np * H_ + k] = __float2half(W_hh[i]);
        return;
    }
    blk -= NB_WHH;
    if (blk < NB_WIH) {
        int i = blk * 256 + threadIdx.x;
        int n = i / KP, c = i % KP;
        int np = ((n & (H_ - 1)) << 2) | (n >> 11);
        float w = (c < E_) ? W_ih[n * E_ + c] : 0.f;
        __half hi = __float2half(w);
        __half lo = __float2half(w - __half2float(hi));
        g_Bcat[(size_t)np * KCAT + c]          = hi;
        g_Bcat[(size_t)np * KCAT + KP + c]     = lo;
        g_Bcat[(size_t)np * KCAT + 2 * KP + c] = hi;
        return;
    }
    blk -= NB_WIH;
    if (blk < NB_X) {
        int i = blk * 256 + threadIdx.x;
        int row = i / KP, c = i % KP;
        int tok = tokens[row];
        float v = (c < E_) ? embed[(size_t)tok * E_ + c] : 0.f;
        __half hi = __float2half(v);
        __half lo = __float2half(v - __half2float(hi));
        g_Acat[(size_t)row * KCAT + c]          = hi;
        g_Acat[(size_t)row * KCAT + KP + c]     = hi;
        g_Acat[(size_t)row * KCAT + 2 * KP + c] = lo;
        return;
    }
    blk -= NB_X;
    if (blk < 1024) {
        int i = blk * 256 + threadIdx.x;
        g_c[i] = 0.f;
        g_h16[i] = __float2half(0.f);
        return;
    }
    blk -= 1024;
    {
        int i = blk * 256 + threadIdx.x;
        if (i < G4) g_bias[i] = b_ih[i] + b_hh[i];
    }
}

// ---------------- Xg GEMM (C[M,N]=A@B^T, tile 128x64, runs once) ----------------
__global__ __launch_bounds__(256) void gemm_kernel(
    const __half* __restrict__ A, const __half* __restrict__ B, float* __restrict__ C,
    int lda, int ldb, int ldc, int K)
{
    __shared__ __half As[128][72];
    __shared__ __half Bs[64][72];
    int tid = threadIdx.x, lane = tid & 31, warp = tid >> 5;
    int wm = warp & 3, wn = warp >> 2;
    int m0 = blockIdx.y * 128, n0 = blockIdx.x * 64;

    float acc[2][4][4];
#pragma unroll
    for (int mi = 0; mi < 2; mi++)
#pragma unroll
        for (int ni = 0; ni < 4; ni++)
#pragma unroll
            for (int q = 0; q < 4; q++) acc[mi][ni][q] = 0.f;

    uint32_t asB = smemAddr(As), bsB = smemAddr(Bs);
    uint32_t aRowByte = (uint32_t)(wm * 32 + (lane & 15)) * 144;
    uint32_t aColByte = (uint32_t)((lane >> 4) << 3) * 2;
    uint32_t bRowByte = (uint32_t)(wn * 32 + ((lane >> 4) & 1) * 8 + (lane & 7)) * 144;
    uint32_t bColByte = (uint32_t)(((lane >> 3) & 1) << 3) * 2;

    for (int k0 = 0; k0 < K; k0 += 64) {
#pragma unroll
        for (int i = 0; i < 4; i++) {
            int v = tid + i * 256; int r = v >> 3, cc = (v & 7) << 3;
            *(uint4*)&As[r][cc] = *(const uint4*)&A[(size_t)(m0 + r) * lda + k0 + cc];
        }
#pragma unroll
        for (int i = 0; i < 2; i++) {
            int v = tid + i * 256; int r = v >> 3, cc = (v & 7) << 3;
            *(uint4*)&Bs[r][cc] = *(const uint4*)&B[(size_t)(n0 + r) * ldb + k0 + cc];
        }
        __syncthreads();
#pragma unroll
        for (int ks = 0; ks < 4; ks++) {
            uint32_t a[2][4], b[2][4];
            uint32_t ka = (uint32_t)ks * 32;
            ldsm4(a[0], asB + aRowByte + ka + aColByte);
            ldsm4(a[1], asB + aRowByte + 16u * 144 + ka + aColByte);
            ldsm4(b[0], bsB + bRowByte + ka + bColByte);
            ldsm4(b[1], bsB + bRowByte + 16u * 144 + ka + bColByte);
#pragma unroll
            for (int mi = 0; mi < 2; mi++)
#pragma unroll
                for (int ni = 0; ni < 4; ni++)
                    mma16816(acc[mi][ni], a[mi], &b[ni >> 1][(ni & 1) * 2]);
        }
        __syncthreads();
    }
#pragma unroll
    for (int mi = 0; mi < 2; mi++) {
        int row = m0 + wm * 32 + mi * 16 + (lane >> 2);
#pragma unroll
        for (int ni = 0; ni < 4; ni++) {
            int col = n0 + wn * 32 + ni * 8 + ((lane & 3) << 1);
            float* cp = C + (size_t)row * ldc + col;
            cp[0] = acc[mi][ni][0]; cp[1] = acc[mi][ni][1];
            cp += (size_t)ldc * 8;
            cp[0] = acc[mi][ni][2]; cp[1] = acc[mi][ni][3];
        }
    }
}

// ---------------- fused LSTM step kernel ----------------
// grid 128 CTAs x 256 thr. CTA owns gate rows n0..n0+63 = hidden units j0..j0+15.
// Xg slice prefetched to smem (group 0) overlapping the GEMM; 4-stage cp.async
// pipeline (depth 2); fused pointwise epilogue.
__global__ __launch_bounds__(256, 1) void lstm_step(
    int s, const int* __restrict__ lens, float* __restrict__ out)
{
    extern __shared__ char dsm[];
    __shared__ float Cs[128][68];
    __shared__ float sBias[NT];

    const int tid = threadIdx.x, lane = tid & 31, warp = tid >> 5;
    const int wm = warp & 3, wn = warp >> 2;
    const int cta = blockIdx.x;
    const int n0 = cta * NT;
    const int j0 = cta * JT;

    const uint32_t dynB = smemAddr(dsm);
    const uint32_t xgB  = dynB + XG_OFF;

    if (tid < NT) sBias[tid] = g_bias[(tid & 3) * H_ + j0 + (tid >> 2)];

    // ---- group 0: prefetch this step's Xg slice (128 rows x 256B) ----
    {
        int row = tid >> 1, half = tid & 1;
        int rb = row & 63;
        int rt = (row < 64) ? s : (T_ - 1 - s);
        const float* src = g_Xg + (size_t)(rt * B_ + rb) * G4 + 4 * j0 + half * 32;
        uint32_t dst = xgB + (uint32_t)(row * 256 + half * 128);
#pragma unroll
        for (int k = 0; k < 8; k++) CP16(dst + k * 16, src + k * 4);
    }
    CP_COMMIT();

    // loader offsets
    uint32_t aDst[4]; const __half* aSrc[4];
#pragma unroll
    for (int i = 0; i < 4; i++) {
        int v = tid + i * 256, r = v >> 3, sg = v & 7;
        aDst[i] = (uint32_t)(r * 144 + sg * 16);
        aSrc[i] = g_h16 + (size_t)r * H_ + sg * 8;
    }
    uint32_t bDst[2]; const __half* bSrc[2];
#pragma unroll
    for (int i = 0; i < 2; i++) {
        int v = tid + i * 256, r = v >> 3, sg = v & 7;
        bDst[i] = (uint32_t)(r * 144 + sg * 16);
        bSrc[i] = g_Whh16 + (size_t)(n0 + r) * H_ + sg * 8;
    }

    const uint32_t aRowByte = (uint32_t)(wm * 32 + (lane & 15)) * 144;
    const uint32_t aColByte = (uint32_t)((lane >> 4) << 3) * 2;
    const uint32_t bRowByte = (uint32_t)(wn * 32 + ((lane >> 4) & 1) * 8 + (lane & 7)) * 144;
    const uint32_t bColByte = (uint32_t)(((lane >> 3) & 1) << 3) * 2;

    float acc[2][4][4];
#pragma unroll
    for (int mi = 0; mi < 2; mi++)
#pragma unroll
        for (int ni = 0; ni < 4; ni++)
#pragma unroll
            for (int q = 0; q < 4; q++) acc[mi][ni][q] = 0.f;

    // prologue: stages 0..2 <- chunks 0..2
#pragma unroll
    for (int p = 0; p < 3; p++) {
        uint32_t aB = dynB + p * STAGE_BYTES, bB = aB + A_BYTES;
#pragma unroll
        for (int i = 0; i < 4; i++) CP16(aB + aDst[i], aSrc[i] + p * 64);
#pragma unroll
        for (int i = 0; i < 2; i++) CP16(bB + bDst[i], bSrc[i] + p * 64);
        CP_COMMIT();
    }

    for (int ck = 0; ck < 32; ck++) {
        if (ck <= 29) CP_WAIT(2); else if (ck == 30) CP_WAIT(1); else CP_WAIT(0);
        __syncthreads();
        if (ck + 3 < 32) {
            int st = (ck + 3) & 3;
            uint32_t aB = dynB + st * STAGE_BYTES, bB = aB + A_BYTES;
#pragma unroll
            for (int i = 0; i < 4; i++) CP16(aB + aDst[i], aSrc[i] + (ck + 3) * 64);
#pragma unroll
            for (int i = 0; i < 2; i++) CP16(bB + bDst[i], bSrc[i] + (ck + 3) * 64);
            CP_COMMIT();
        }
        uint32_t asB = dynB + (ck & 3) * STAGE_BYTES;
        uint32_t bsB = asB + A_BYTES;
#pragma unroll
        for (int ks = 0; ks < 4; ks++) {
            uint32_t a[2][4], b[2][4];
            uint32_t ka = (uint32_t)ks * 32;
            ldsm4(a[0], asB + aRowByte + ka + aColByte);
            ldsm4(a[1], asB + aRowByte + 16u * 144 + ka + aColByte);
            ldsm4(b[0], bsB + bRowByte + ka + bColByte);
            ldsm4(b[1], bsB + bRowByte + 16u * 144 + ka + bColByte);
#pragma unroll
            for (int mi = 0; mi < 2; mi++)
#pragma unroll
                for (int ni = 0; ni < 4; ni++)
                    mma16816(acc[mi][ni], a[mi], &b[ni >> 1][(ni & 1) * 2]);
        }
    }

    // acc -> smem C
    __syncthreads();
#pragma unroll
    for (int mi = 0; mi < 2; mi++) {
        int row = wm * 32 + mi * 16 + (lane >> 2);
#pragma unroll
        for (int ni = 0; ni < 4; ni++) {
            int col = wn * 32 + ni * 8 + ((lane & 3) << 1);
            Cs[row][col]     = acc[mi][ni][0];
            Cs[row][col + 1] = acc[mi][ni][1];
            Cs[row + 8][col]     = acc[mi][ni][2];
            Cs[row + 8][col + 1] = acc[mi][ni][3];
        }
    }
    __syncthreads();

    // -------- fused pointwise: thread -> 8 hidden units of batch row pm --------
    const int pm = tid & 127;
    const int ph = tid >> 7;
    const int pb = pm & 63;
    const int myLen = lens[pb];
    const float* xg = (const float*)(dsm + XG_OFF) + pm * 64 + ph * 32;
    float* cptr = g_c + (size_t)pm * H_ + j0 + ph * 8;
    float4 c0 = *(const float4*)(cptr);
    float4 c1 = *(const float4*)(cptr + 4);
    float cst[8] = {c0.x, c0.y, c0.z, c0.w, c1.x, c1.y, c1.z, c1.w};

    __half hv8[8];
#pragma unroll
    for (int q = 0; q < 8; q++) {
        int jl = ph * 8 + q, nl = 4 * jl;
        float4 z  = *(const float4*)&Cs[pm][nl];
        float4 x4 = *(const float4*)(xg + 4 * q);
        float zi = z.x + x4.x + sBias[nl + 0];
        float zf = z.y + x4.y + sBias[nl + 1];
        float zg = z.z + x4.z + sBias[nl + 2];
        float zo = z.w + x4.w + sBias[nl + 3];
        float cv = sigm(zf) * cst[q] + sigm(zi) * tanh_f(zg);
        float hv = sigm(zo) * tanh_f(cv);
        cst[q] = cv;
        hv8[q] = __float2half(hv);
        if (pm < 64) {
            if (myLen == s + 1) out[(size_t)pb * (2 * H_) + j0 + jl] = hv;
        } else if (s == T_ - 1) {
            out[(size_t)pb * (2 * H_) + H_ + j0 + jl] = hv;
        }
    }
    *(float4*)(cptr)     = make_float4(cst[0], cst[1], cst[2], cst[3]);
    *(float4*)(cptr + 4) = make_float4(cst[4], cst[5], cst[6], cst[7]);
    *(uint4*)&g_h16[(size_t)pm * H_ + j0 + ph * 8] = *(uint4*)hv8;
}

// ---------------- launch ----------------
extern "C" void kernel_launch(void* const* d_in, const int* in_sizes, int n_in,
                              void* d_out, int out_size)
{
    (void)in_sizes; (void)n_in; (void)out_size;
    const int*   tokens = (const int*)  d_in[0];
    const int*   lens   = (const int*)  d_in[1];
    const float* embed  = (const float*)d_in[2];
    const float* W_ih   = (const float*)d_in[3];
    const float* W_hh   = (const float*)d_in[4];
    const float* b_ih   = (const float*)d_in[5];
    const float* b_hh   = (const float*)d_in[6];
    float* out = (float*)d_out;

    cudaFuncSetAttribute(lstm_step,
                         cudaFuncAttributeMaxDynamicSharedMemorySize, DYN_SMEM);

    void *pA, *pB, *pXg;
    cudaGetSymbolAddress(&pA, g_Acat);
    cudaGetSymbolAddress(&pB, g_Bcat);
    cudaGetSymbolAddress(&pXg, g_Xg);

    prep_all<<<NB_WHH + NB_WIH + NB_X + NB_MISC, 256>>>(
        tokens, embed, W_ih, W_hh, b_ih, b_hh);

    gemm_kernel<<<dim3(G4 / 64, TB / 128), 256>>>(
        (const __half*)pA, (const __half*)pB, (float*)pXg, KCAT, KCAT, G4, KCAT);

    for (int s = 0; s < T_; s++)
        lstm_step<<<NCTA, 256, DYN_SMEM>>>(s, lens, out);
}

// round 10
// speedup vs baseline: 1.0421x; 1.0091x over previous
#include <cuda_runtime.h>
#include <cuda_fp16.h>
#include <cstdint>

#define T_   128
#define B_   64
#define E_   300
#define H_   2048
#define G4   8192
#define TB   8192
#define KP   320
#define KCAT 960

// step-kernel config
#define NCTA   128
#define NT     64                 // gate rows per CTA
#define JT     16                 // hidden units per CTA
#define STAGES 4
#define A_BYTES 18432             // 128 rows x 144B
#define B_BYTES 9216              // 64 rows x 144B
#define STAGE_BYTES (A_BYTES + B_BYTES)     // 27648
#define XG_OFF  (STAGES * STAGE_BYTES)      // 110592
#define XG_BYTES 32768                      // 128 rows x 256B
#define DYN_SMEM (XG_OFF + XG_BYTES)        // 143360  (same as passing R7)

// ---------------- scratch ----------------
__device__ __align__(256) __half g_Acat[(size_t)TB * KCAT];
__device__ __align__(256) __half g_Bcat[(size_t)G4 * KCAT];
__device__ __align__(256) __half g_Whh16[(size_t)G4 * H_];   // gate-interleaved rows
__device__ __align__(256) float  g_Xg[(size_t)TB * G4];      // [t*B+b][np] np=4j+g
__device__ __align__(256) float  g_bias[G4];
__device__ __align__(256) float  g_c[128 * H_];              // cell state
__device__ __align__(256) __half g_h16[128 * H_];            // hidden state

// ---------------- helpers ----------------
__device__ __forceinline__ uint32_t smemAddr(const void* p) {
    return (uint32_t)__cvta_generic_to_shared(p);
}
__device__ __forceinline__ void ldsm4(uint32_t r[4], uint32_t addr) {
    asm volatile("ldmatrix.sync.aligned.m8n8.x4.shared.b16 {%0,%1,%2,%3}, [%4];\n"
                 : "=r"(r[0]), "=r"(r[1]), "=r"(r[2]), "=r"(r[3]) : "r"(addr));
}
__device__ __forceinline__ void mma16816(float* c, const uint32_t* a, const uint32_t* b) {
    asm volatile("mma.sync.aligned.m16n8k16.row.col.f32.f16.f16.f32 "
                 "{%0,%1,%2,%3}, {%4,%5,%6,%7}, {%8,%9}, {%0,%1,%2,%3};\n"
                 : "+f"(c[0]), "+f"(c[1]), "+f"(c[2]), "+f"(c[3])
                 : "r"(a[0]), "r"(a[1]), "r"(a[2]), "r"(a[3]), "r"(b[0]), "r"(b[1]));
}
#define CP16(dst, src) asm volatile("cp.async.cg.shared.global [%0], [%1], 16;\n" :: "r"(dst), "l"(src))
#define CP_COMMIT()    asm volatile("cp.async.commit_group;\n" ::: "memory")
#define CP_WAIT(N)     asm volatile("cp.async.wait_group %0;\n" :: "n"(N) : "memory")

__device__ __forceinline__ float sigm(float x) { return 1.f / (1.f + __expf(-x)); }
__device__ __forceinline__ float tanh_f(float x) { return 2.f / (1.f + __expf(-2.f * x)) - 1.f; }

// ---------------- merged prep kernel (block-range dispatch) ----------------
#define NB_WHH  65536     // G4*H/256
#define NB_WIH  10240     // G4*KP/256
#define NB_X    10240     // TB*KP/256
#define NB_MISC 1056      // 1024 (state) + 32 (bias)
__global__ void prep_all(const int* __restrict__ tokens, const float* __restrict__ embed,
                         const float* __restrict__ W_ih, const float* __restrict__ W_hh,
                         const float* __restrict__ b_ih, const float* __restrict__ b_hh)
{
    int blk = blockIdx.x;
    if (blk < NB_WHH) {
        int i = blk * 256 + threadIdx.x;
        int n = i >> 11, k = i & (H_ - 1);
        int np = ((n & (H_ - 1)) << 2) | (n >> 11);
        g_Whh16[(size_t)np * H_ + k] = __float2half(W_hh[i]);
        return;
    }
    blk -= NB_WHH;
    if (blk < NB_WIH) {
        int i = blk * 256 + threadIdx.x;
        int n = i / KP, c = i % KP;
        int np = ((n & (H_ - 1)) << 2) | (n >> 11);
        float w = (c < E_) ? W_ih[n * E_ + c] : 0.f;
        __half hi = __float2half(w);
        __half lo = __float2half(w - __half2float(hi));
        g_Bcat[(size_t)np * KCAT + c]          = hi;
        g_Bcat[(size_t)np * KCAT + KP + c]     = lo;
        g_Bcat[(size_t)np * KCAT + 2 * KP + c] = hi;
        return;
    }
    blk -= NB_WIH;
    if (blk < NB_X) {
        int i = blk * 256 + threadIdx.x;
        int row = i / KP, c = i % KP;
        int tok = tokens[row];
        float v = (c < E_) ? embed[(size_t)tok * E_ + c] : 0.f;
        __half hi = __float2half(v);
        __half lo = __float2half(v - __half2float(hi));
        g_Acat[(size_t)row * KCAT + c]          = hi;
        g_Acat[(size_t)row * KCAT + KP + c]     = hi;
        g_Acat[(size_t)row * KCAT + 2 * KP + c] = lo;
        return;
    }
    blk -= NB_X;
    if (blk < 1024) {
        int i = blk * 256 + threadIdx.x;
        g_c[i] = 0.f;
        g_h16[i] = __float2half(0.f);
        return;
    }
    blk -= 1024;
    {
        int i = blk * 256 + threadIdx.x;
        if (i < G4) g_bias[i] = b_ih[i] + b_hh[i];
    }
}

// ---------------- Xg GEMM (C[M,N]=A@B^T, tile 128x64, runs once) ----------------
__global__ __launch_bounds__(256) void gemm_kernel(
    const __half* __restrict__ A, const __half* __restrict__ B, float* __restrict__ C,
    int lda, int ldb, int ldc, int K)
{
    __shared__ __half As[128][72];
    __shared__ __half Bs[64][72];
    int tid = threadIdx.x, lane = tid & 31, warp = tid >> 5;
    int wm = warp & 3, wn = warp >> 2;
    int m0 = blockIdx.y * 128, n0 = blockIdx.x * 64;

    float acc[2][4][4];
#pragma unroll
    for (int mi = 0; mi < 2; mi++)
#pragma unroll
        for (int ni = 0; ni < 4; ni++)
#pragma unroll
            for (int q = 0; q < 4; q++) acc[mi][ni][q] = 0.f;

    uint32_t asB = smemAddr(As), bsB = smemAddr(Bs);
    uint32_t aRowByte = (uint32_t)(wm * 32 + (lane & 15)) * 144;
    uint32_t aColByte = (uint32_t)((lane >> 4) << 3) * 2;
    uint32_t bRowByte = (uint32_t)(wn * 32 + ((lane >> 4) & 1) * 8 + (lane & 7)) * 144;
    uint32_t bColByte = (uint32_t)(((lane >> 3) & 1) << 3) * 2;

    for (int k0 = 0; k0 < K; k0 += 64) {
#pragma unroll
        for (int i = 0; i < 4; i++) {
            int v = tid + i * 256; int r = v >> 3, cc = (v & 7) << 3;
            *(uint4*)&As[r][cc] = *(const uint4*)&A[(size_t)(m0 + r) * lda + k0 + cc];
        }
#pragma unroll
        for (int i = 0; i < 2; i++) {
            int v = tid + i * 256; int r = v >> 3, cc = (v & 7) << 3;
            *(uint4*)&Bs[r][cc] = *(const uint4*)&B[(size_t)(n0 + r) * ldb + k0 + cc];
        }
        __syncthreads();
#pragma unroll
        for (int ks = 0; ks < 4; ks++) {
            uint32_t a[2][4], b[2][4];
            uint32_t ka = (uint32_t)ks * 32;
            ldsm4(a[0], asB + aRowByte + ka + aColByte);
            ldsm4(a[1], asB + aRowByte + 16u * 144 + ka + aColByte);
            ldsm4(b[0], bsB + bRowByte + ka + bColByte);
            ldsm4(b[1], bsB + bRowByte + 16u * 144 + ka + bColByte);
#pragma unroll
            for (int mi = 0; mi < 2; mi++)
#pragma unroll
                for (int ni = 0; ni < 4; ni++)
                    mma16816(acc[mi][ni], a[mi], &b[ni >> 1][(ni & 1) * 2]);
        }
        __syncthreads();
    }
#pragma unroll
    for (int mi = 0; mi < 2; mi++) {
        int row = m0 + wm * 32 + mi * 16 + (lane >> 2);
#pragma unroll
        for (int ni = 0; ni < 4; ni++) {
            int col = n0 + wn * 32 + ni * 8 + ((lane & 3) << 1);
            float* cp = C + (size_t)row * ldc + col;
            cp[0] = acc[mi][ni][0]; cp[1] = acc[mi][ni][1];
            cp += (size_t)ldc * 8;
            cp[0] = acc[mi][ni][2]; cp[1] = acc[mi][ni][3];
        }
    }
}

// ---------------- fused LSTM step kernel ----------------
// 128 CTAs x 512 thr (16 warps: 8 along M x 2 along N, warp tile 16x32).
// R7-proven schedule: 4 stages, prologue 3 chunks, prefetch depth 2.
// Xg slice prefetched in group 0; fused pointwise epilogue (4 units/thread).
__global__ __launch_bounds__(512, 1) void lstm_step(
    int s, const int* __restrict__ lens, float* __restrict__ out)
{
    extern __shared__ char dsm[];
    __shared__ float Cs[128][68];
    __shared__ float sBias[NT];

    const int tid = threadIdx.x, lane = tid & 31, warp = tid >> 5;
    const int wm = warp & 7;          // m16 block
    const int wn = warp >> 3;         // n32 half
    const int cta = blockIdx.x;
    const int n0 = cta * NT;
    const int j0 = cta * JT;

    const uint32_t dynB = smemAddr(dsm);
    const uint32_t xgB  = dynB + XG_OFF;

    if (tid < NT) sBias[tid] = g_bias[(tid & 3) * H_ + j0 + (tid >> 2)];

    // ---- group 0: prefetch this step's Xg slice (128 rows x 256B = 2048 units) ----
#pragma unroll
    for (int k = 0; k < 4; k++) {
        int u = tid * 4 + k;                 // 16B unit
        int row = u >> 4, seg = u & 15;
        int rb = row & 63;
        int rt = (row < 64) ? s : (T_ - 1 - s);
        const float* src = g_Xg + (size_t)(rt * B_ + rb) * G4 + 4 * j0 + seg * 4;
        CP16(xgB + (uint32_t)u * 16, src);
    }
    CP_COMMIT();

    // loader offsets (A: 1024 units / 512 thr = 2 each; B: 512 units = 1 each)
    uint32_t aDst[2]; const __half* aSrc[2];
#pragma unroll
    for (int i = 0; i < 2; i++) {
        int v = tid + i * 512, r = v >> 3, sg = v & 7;
        aDst[i] = (uint32_t)(r * 144 + sg * 16);
        aSrc[i] = g_h16 + (size_t)r * H_ + sg * 8;
    }
    uint32_t bDst; const __half* bSrc;
    {
        int r = tid >> 3, sg = tid & 7;
        bDst = (uint32_t)(r * 144 + sg * 16);
        bSrc = g_Whh16 + (size_t)(n0 + r) * H_ + sg * 8;
    }

    // ldsm addressing (within a stage)
    const uint32_t aRowByte = (uint32_t)(wm * 16 + (lane & 15)) * 144;
    const uint32_t aColByte = (uint32_t)((lane >> 4) << 3) * 2;
    const uint32_t bRowByte0 = (uint32_t)(wn * 32 + ((lane >> 4) & 1) * 8 + (lane & 7)) * 144;
    const uint32_t bColByte  = (uint32_t)(((lane >> 3) & 1) << 3) * 2;

    float acc[4][4];
#pragma unroll
    for (int ni = 0; ni < 4; ni++)
#pragma unroll
        for (int q = 0; q < 4; q++) acc[ni][q] = 0.f;

    // prologue: stages 0..2 <- chunks 0..2
#pragma unroll
    for (int p = 0; p < 3; p++) {
        uint32_t aB = dynB + p * STAGE_BYTES, bB = aB + A_BYTES;
#pragma unroll
        for (int i = 0; i < 2; i++) CP16(aB + aDst[i], aSrc[i] + p * 64);
        CP16(bB + bDst, bSrc + p * 64);
        CP_COMMIT();
    }

    int stComp = 0, stLoad = 3;
    for (int ck = 0; ck < 32; ck++) {
        if (ck <= 29) CP_WAIT(2); else if (ck == 30) CP_WAIT(1); else CP_WAIT(0);
        __syncthreads();
        if (ck + 3 < 32) {
            uint32_t aB = dynB + stLoad * STAGE_BYTES, bB = aB + A_BYTES;
#pragma unroll
            for (int i = 0; i < 2; i++) CP16(aB + aDst[i], aSrc[i] + (ck + 3) * 64);
            CP16(bB + bDst, bSrc + (ck + 3) * 64);
            CP_COMMIT();
            if (++stLoad == STAGES) stLoad = 0;
        }
        uint32_t asB = dynB + stComp * STAGE_BYTES;
        uint32_t bsB = asB + A_BYTES;
        if (++stComp == STAGES) stComp = 0;
#pragma unroll
        for (int ks = 0; ks < 4; ks++) {
            uint32_t a[4], b[2][4];
            uint32_t ka = (uint32_t)ks * 32;
            ldsm4(a, asB + aRowByte + ka + aColByte);
            ldsm4(b[0], bsB + bRowByte0 + ka + bColByte);
            ldsm4(b[1], bsB + bRowByte0 + 16u * 144 + ka + bColByte);
#pragma unroll
            for (int ni = 0; ni < 4; ni++)
                mma16816(acc[ni], a, &b[ni >> 1][(ni & 1) * 2]);
        }
    }

    // acc -> smem C
    __syncthreads();
    {
        int row = wm * 16 + (lane >> 2);
#pragma unroll
        for (int ni = 0; ni < 4; ni++) {
            int col = wn * 32 + ni * 8 + ((lane & 3) << 1);
            Cs[row][col]     = acc[ni][0];
            Cs[row][col + 1] = acc[ni][1];
            Cs[row + 8][col]     = acc[ni][2];
            Cs[row + 8][col + 1] = acc[ni][3];
        }
    }
    __syncthreads();

    // -------- fused pointwise: thread -> 4 hidden units of batch row pm --------
    const int pm = tid & 127;
    const int pq = tid >> 7;             // quarter (0..3): units pq*4..pq*4+3
    const int pb = pm & 63;
    const int myLen = lens[pb];
    const float* xg = (const float*)(dsm + XG_OFF) + pm * 64 + pq * 16;
    float* cptr = g_c + (size_t)pm * H_ + j0 + pq * 4;
    float4 c0 = *(const float4*)(cptr);
    float cst[4] = {c0.x, c0.y, c0.z, c0.w};

    __half hv4[4];
#pragma unroll
    for (int q = 0; q < 4; q++) {
        int jl = pq * 4 + q, nl = 4 * jl;
        float4 z  = *(const float4*)&Cs[pm][nl];
        float4 x4 = *(const float4*)(xg + 4 * q);
        float zi = z.x + x4.x + sBias[nl + 0];
        float zf = z.y + x4.y + sBias[nl + 1];
        float zg = z.z + x4.z + sBias[nl + 2];
        float zo = z.w + x4.w + sBias[nl + 3];
        float cv = sigm(zf) * cst[q] + sigm(zi) * tanh_f(zg);
        float hv = sigm(zo) * tanh_f(cv);
        cst[q] = cv;
        hv4[q] = __float2half(hv);
        if (pm < 64) {
            if (myLen == s + 1) out[(size_t)pb * (2 * H_) + j0 + jl] = hv;
        } else if (s == T_ - 1) {
            out[(size_t)pb * (2 * H_) + H_ + j0 + jl] = hv;
        }
    }
    *(float4*)(cptr) = make_float4(cst[0], cst[1], cst[2], cst[3]);
    *(uint2*)&g_h16[(size_t)pm * H_ + j0 + pq * 4] = *(uint2*)hv4;
}

// ---------------- launch ----------------
extern "C" void kernel_launch(void* const* d_in, const int* in_sizes, int n_in,
                              void* d_out, int out_size)
{
    (void)in_sizes; (void)n_in; (void)out_size;
    const int*   tokens = (const int*)  d_in[0];
    const int*   lens   = (const int*)  d_in[1];
    const float* embed  = (const float*)d_in[2];
    const float* W_ih   = (const float*)d_in[3];
    const float* W_hh   = (const float*)d_in[4];
    const float* b_ih   = (const float*)d_in[5];
    const float* b_hh   = (const float*)d_in[6];
    float* out = (float*)d_out;

    cudaFuncSetAttribute(lstm_step,
                         cudaFuncAttributeMaxDynamicSharedMemorySize, DYN_SMEM);

    void *pA, *pB, *pXg;
    cudaGetSymbolAddress(&pA, g_Acat);
    cudaGetSymbolAddress(&pB, g_Bcat);
    cudaGetSymbolAddress(&pXg, g_Xg);

    prep_all<<<NB_WHH + NB_WIH + NB_X + NB_MISC, 256>>>(
        tokens, embed, W_ih, W_hh, b_ih, b_hh);

    gemm_kernel<<<dim3(G4 / 64, TB / 128), 256>>>(
        (const __half*)pA, (const __half*)pB, (float*)pXg, KCAT, KCAT, G4, KCAT);

    for (int s = 0; s < T_; s++)
        lstm_step<<<NCTA, 512, DYN_SMEM>>>(s, lens, out);
}

// round 11
// speedup vs baseline: 1.1885x; 1.1405x over previous
#include <cuda_runtime.h>
#include <cuda_fp16.h>
#include <cstdint>

#define T_   128
#define B_   64
#define E_   300
#define H_   2048
#define G4   8192
#define TB   8192
#define KP   320
#define KCAT 960

// step-kernel config: two independent K-groups, each 8 warps, 2 stages
#define NCTA   128
#define NT     64                 // gate rows per CTA
#define JT     16                 // hidden units per CTA
#define A_BYTES 18432             // 128 rows x 144B
#define B_BYTES 9216              // 64 rows x 144B
#define STAGE_BYTES (A_BYTES + B_BYTES)     // 27648
#define XG_BYTES 32768                      // 128 rows x 256B
#define DYN_SMEM (XG_BYTES + 4 * STAGE_BYTES)  // 143360 (proven size)
#define KHALF  1024               // K per group
#define NCHUNK 16                 // K64 chunks per group

// ---------------- scratch ----------------
__device__ __align__(256) __half g_Acat[(size_t)TB * KCAT];
__device__ __align__(256) __half g_Bcat[(size_t)G4 * KCAT];
__device__ __align__(256) __half g_Whh16[(size_t)G4 * H_];   // gate-interleaved rows
__device__ __align__(256) float  g_Xg[(size_t)TB * G4];      // [t*B+b][np] np=4j+g
__device__ __align__(256) float  g_bias[G4];
__device__ __align__(256) float  g_c[128 * H_];              // cell state
__device__ __align__(256) __half g_h16[128 * H_];            // hidden state

// ---------------- helpers ----------------
__device__ __forceinline__ uint32_t smemAddr(const void* p) {
    return (uint32_t)__cvta_generic_to_shared(p);
}
__device__ __forceinline__ void ldsm4(uint32_t r[4], uint32_t addr) {
    asm volatile("ldmatrix.sync.aligned.m8n8.x4.shared.b16 {%0,%1,%2,%3}, [%4];\n"
                 : "=r"(r[0]), "=r"(r[1]), "=r"(r[2]), "=r"(r[3]) : "r"(addr));
}
__device__ __forceinline__ void mma16816(float* c, const uint32_t* a, const uint32_t* b) {
    asm volatile("mma.sync.aligned.m16n8k16.row.col.f32.f16.f16.f32 "
                 "{%0,%1,%2,%3}, {%4,%5,%6,%7}, {%8,%9}, {%0,%1,%2,%3};\n"
                 : "+f"(c[0]), "+f"(c[1]), "+f"(c[2]), "+f"(c[3])
                 : "r"(a[0]), "r"(a[1]), "r"(a[2]), "r"(a[3]), "r"(b[0]), "r"(b[1]));
}
#define CP16(dst, src) asm volatile("cp.async.cg.shared.global [%0], [%1], 16;\n" :: "r"(dst), "l"(src))
#define CP_COMMIT()    asm volatile("cp.async.commit_group;\n" ::: "memory")
#define CP_WAIT(N)     asm volatile("cp.async.wait_group %0;\n" :: "n"(N) : "memory")
#define BARG(id)       asm volatile("bar.sync %0, %1;" :: "r"(id), "r"(256) : "memory")

__device__ __forceinline__ float sigm(float x) { return 1.f / (1.f + __expf(-x)); }
__device__ __forceinline__ float tanh_f(float x) { return 2.f / (1.f + __expf(-2.f * x)) - 1.f; }

// ---------------- merged prep kernel (block-range dispatch) ----------------
#define NB_WHH  65536     // G4*H/256
#define NB_WIH  10240     // G4*KP/256
#define NB_X    10240     // TB*KP/256
#define NB_MISC 1056      // 1024 (state) + 32 (bias)
__global__ void prep_all(const int* __restrict__ tokens, const float* __restrict__ embed,
                         const float* __restrict__ W_ih, const float* __restrict__ W_hh,
                         const float* __restrict__ b_ih, const float* __restrict__ b_hh)
{
    int blk = blockIdx.x;
    if (blk < NB_WHH) {
        int i = blk * 256 + threadIdx.x;
        int n = i >> 11, k = i & (H_ - 1);
        int np = ((n & (H_ - 1)) << 2) | (n >> 11);
        g_Whh16[(size_t)np * H_ + k] = __float2half(W_hh[i]);
        return;
    }
    blk -= NB_WHH;
    if (blk < NB_WIH) {
        int i = blk * 256 + threadIdx.x;
        int n = i / KP, c = i % KP;
        int np = ((n & (H_ - 1)) << 2) | (n >> 11);
        float w = (c < E_) ? W_ih[n * E_ + c] : 0.f;
        __half hi = __float2half(w);
        __half lo = __float2half(w - __half2float(hi));
        g_Bcat[(size_t)np * KCAT + c]          = hi;
        g_Bcat[(size_t)np * KCAT + KP + c]     = lo;
        g_Bcat[(size_t)np * KCAT + 2 * KP + c] = hi;
        return;
    }
    blk -= NB_WIH;
    if (blk < NB_X) {
        int i = blk * 256 + threadIdx.x;
        int row = i / KP, c = i % KP;
        int tok = tokens[row];
        float v = (c < E_) ? embed[(size_t)tok * E_ + c] : 0.f;
        __half hi = __float2half(v);
        __half lo = __float2half(v - __half2float(hi));
        g_Acat[(size_t)row * KCAT + c]          = hi;
        g_Acat[(size_t)row * KCAT + KP + c]     = hi;
        g_Acat[(size_t)row * KCAT + 2 * KP + c] = lo;
        return;
    }
    blk -= NB_X;
    if (blk < 1024) {
        int i = blk * 256 + threadIdx.x;
        g_c[i] = 0.f;
        g_h16[i] = __float2half(0.f);
        return;
    }
    blk -= 1024;
    {
        int i = blk * 256 + threadIdx.x;
        if (i < G4) g_bias[i] = b_ih[i] + b_hh[i];
    }
}

// ---------------- Xg GEMM (C[M,N]=A@B^T, tile 128x64, runs once) ----------------
__global__ __launch_bounds__(256) void gemm_kernel(
    const __half* __restrict__ A, const __half* __restrict__ B, float* __restrict__ C,
    int lda, int ldb, int ldc, int K)
{
    __shared__ __half As[128][72];
    __shared__ __half Bs[64][72];
    int tid = threadIdx.x, lane = tid & 31, warp = tid >> 5;
    int wm = warp & 3, wn = warp >> 2;
    int m0 = blockIdx.y * 128, n0 = blockIdx.x * 64;

    float acc[2][4][4];
#pragma unroll
    for (int mi = 0; mi < 2; mi++)
#pragma unroll
        for (int ni = 0; ni < 4; ni++)
#pragma unroll
            for (int q = 0; q < 4; q++) acc[mi][ni][q] = 0.f;

    uint32_t asB = smemAddr(As), bsB = smemAddr(Bs);
    uint32_t aRowByte = (uint32_t)(wm * 32 + (lane & 15)) * 144;
    uint32_t aColByte = (uint32_t)((lane >> 4) << 3) * 2;
    uint32_t bRowByte = (uint32_t)(wn * 32 + ((lane >> 4) & 1) * 8 + (lane & 7)) * 144;
    uint32_t bColByte = (uint32_t)(((lane >> 3) & 1) << 3) * 2;

    for (int k0 = 0; k0 < K; k0 += 64) {
#pragma unroll
        for (int i = 0; i < 4; i++) {
            int v = tid + i * 256; int r = v >> 3, cc = (v & 7) << 3;
            *(uint4*)&As[r][cc] = *(const uint4*)&A[(size_t)(m0 + r) * lda + k0 + cc];
        }
#pragma unroll
        for (int i = 0; i < 2; i++) {
            int v = tid + i * 256; int r = v >> 3, cc = (v & 7) << 3;
            *(uint4*)&Bs[r][cc] = *(const uint4*)&B[(size_t)(n0 + r) * ldb + k0 + cc];
        }
        __syncthreads();
#pragma unroll
        for (int ks = 0; ks < 4; ks++) {
            uint32_t a[2][4], b[2][4];
            uint32_t ka = (uint32_t)ks * 32;
            ldsm4(a[0], asB + aRowByte + ka + aColByte);
            ldsm4(a[1], asB + aRowByte + 16u * 144 + ka + aColByte);
            ldsm4(b[0], bsB + bRowByte + ka + bColByte);
            ldsm4(b[1], bsB + bRowByte + 16u * 144 + ka + bColByte);
#pragma unroll
            for (int mi = 0; mi < 2; mi++)
#pragma unroll
                for (int ni = 0; ni < 4; ni++)
                    mma16816(acc[mi][ni], a[mi], &b[ni >> 1][(ni & 1) * 2]);
        }
        __syncthreads();
    }
#pragma unroll
    for (int mi = 0; mi < 2; mi++) {
        int row = m0 + wm * 32 + mi * 16 + (lane >> 2);
#pragma unroll
        for (int ni = 0; ni < 4; ni++) {
            int col = n0 + wn * 32 + ni * 8 + ((lane & 3) << 1);
            float* cp = C + (size_t)row * ldc + col;
            cp[0] = acc[mi][ni][0]; cp[1] = acc[mi][ni][1];
            cp += (size_t)ldc * 8;
            cp[0] = acc[mi][ni][2]; cp[1] = acc[mi][ni][3];
        }
    }
}

// ---------------- fused LSTM step kernel ----------------
// 128 CTAs x 512 thr. Warps 0-7 = group 0 (K[0,1024)), warps 8-15 = group 1
// (K[1024,2048)). Each group: independent 2-stage cp.async pipeline + its own
// 256-thread named barrier (no CTA-wide sync in the mainloop). Partials are
// reduced through smem Cs, then fused LSTM pointwise.
__global__ __launch_bounds__(512, 1) void lstm_step(
    int s, const int* __restrict__ lens, float* __restrict__ out)
{
    extern __shared__ char dsm[];
    __shared__ float Cs[128][68];
    __shared__ float sBias[NT];

    const int tid = threadIdx.x, lane = tid & 31;
    const int g    = tid >> 8;           // K-group 0/1
    const int gtid = tid & 255;
    const int gwarp = gtid >> 5;         // 0..7 within group
    const int wm = gwarp & 3;            // 4 along M (warp tile 32x32)
    const int wn = gwarp >> 2;           // 2 along N
    const int cta = blockIdx.x;
    const int n0 = cta * NT;
    const int j0 = cta * JT;
    const int barId = 1 + g;

    const uint32_t dynB = smemAddr(dsm);
    const uint32_t xgB  = dynB;                       // Xg at offset 0
    const uint32_t stB  = dynB + XG_BYTES + (uint32_t)g * 2 * STAGE_BYTES;

    if (tid < NT) sBias[tid] = g_bias[(tid & 3) * H_ + j0 + (tid >> 2)];

    // ---- commit 1 (all threads): prefetch Xg slice (128 rows x 256B) ----
#pragma unroll
    for (int k = 0; k < 4; k++) {
        int u = tid * 4 + k;                 // 16B unit
        int row = u >> 4, seg = u & 15;
        int rb = row & 63;
        int rt = (row < 64) ? s : (T_ - 1 - s);
        const float* src = g_Xg + (size_t)(rt * B_ + rb) * G4 + 4 * j0 + seg * 4;
        CP16(xgB + (uint32_t)u * 16, src);
    }
    CP_COMMIT();

    // loader offsets (per group, 256 threads: A 4 units/thr, B 2 units/thr)
    uint32_t aDst[4]; const __half* aSrc[4];
#pragma unroll
    for (int i = 0; i < 4; i++) {
        int v = gtid + i * 256, r = v >> 3, sg = v & 7;
        aDst[i] = (uint32_t)(r * 144 + sg * 16);
        aSrc[i] = g_h16 + (size_t)r * H_ + g * KHALF + sg * 8;
    }
    uint32_t bDst[2]; const __half* bSrc[2];
#pragma unroll
    for (int i = 0; i < 2; i++) {
        int v = gtid + i * 256, r = v >> 3, sg = v & 7;
        bDst[i] = (uint32_t)(r * 144 + sg * 16);
        bSrc[i] = g_Whh16 + (size_t)(n0 + r) * H_ + g * KHALF + sg * 8;
    }

    // ldsm addressing (within a stage)
    const uint32_t aRowByte = (uint32_t)(wm * 32 + (lane & 15)) * 144;
    const uint32_t aColByte = (uint32_t)((lane >> 4) << 3) * 2;
    const uint32_t bRowByte = (uint32_t)(wn * 32 + ((lane >> 4) & 1) * 8 + (lane & 7)) * 144;
    const uint32_t bColByte = (uint32_t)(((lane >> 3) & 1) << 3) * 2;

    float acc[2][4][4];
#pragma unroll
    for (int mi = 0; mi < 2; mi++)
#pragma unroll
        for (int ni = 0; ni < 4; ni++)
#pragma unroll
            for (int q = 0; q < 4; q++) acc[mi][ni][q] = 0.f;

    // prologue: chunks 0,1 -> stages 0,1 (commits 2,3)
#pragma unroll
    for (int p = 0; p < 2; p++) {
        uint32_t aB = stB + p * STAGE_BYTES, bB = aB + A_BYTES;
#pragma unroll
        for (int i = 0; i < 4; i++) CP16(aB + aDst[i], aSrc[i] + p * 64);
#pragma unroll
        for (int i = 0; i < 2; i++) CP16(bB + bDst[i], bSrc[i] + p * 64);
        CP_COMMIT();
    }

    // -------- mainloop: 16 chunks, group-local barriers only --------
    for (int ck = 0; ck < NCHUNK; ck++) {
        if (ck < NCHUNK - 1) CP_WAIT(1); else CP_WAIT(0);
        BARG(barId);
        uint32_t asB = stB + (ck & 1) * STAGE_BYTES;
        uint32_t bsB = asB + A_BYTES;
#pragma unroll
        for (int ks = 0; ks < 4; ks++) {
            uint32_t a[2][4], b[2][4];
            uint32_t ka = (uint32_t)ks * 32;
            ldsm4(a[0], asB + aRowByte + ka + aColByte);
            ldsm4(a[1], asB + aRowByte + 16u * 144 + ka + aColByte);
            ldsm4(b[0], bsB + bRowByte + ka + bColByte);
            ldsm4(b[1], bsB + bRowByte + 16u * 144 + ka + bColByte);
#pragma unroll
            for (int mi = 0; mi < 2; mi++)
#pragma unroll
                for (int ni = 0; ni < 4; ni++)
                    mma16816(acc[mi][ni], a[mi], &b[ni >> 1][(ni & 1) * 2]);
        }
        BARG(barId);
        if (ck + 2 < NCHUNK) {
            uint32_t aB = stB + (ck & 1) * STAGE_BYTES, bB = aB + A_BYTES;
#pragma unroll
            for (int i = 0; i < 4; i++) CP16(aB + aDst[i], aSrc[i] + (ck + 2) * 64);
#pragma unroll
            for (int i = 0; i < 2; i++) CP16(bB + bDst[i], bSrc[i] + (ck + 2) * 64);
            CP_COMMIT();
        }
    }

    // -------- reduce the two K-halves through Cs --------
    if (g == 0) {      // group 0 stores its partial
#pragma unroll
        for (int mi = 0; mi < 2; mi++) {
            int row = wm * 32 + mi * 16 + (lane >> 2);
#pragma unroll
            for (int ni = 0; ni < 4; ni++) {
                int col = wn * 32 + ni * 8 + ((lane & 3) << 1);
                Cs[row][col]     = acc[mi][ni][0];
                Cs[row][col + 1] = acc[mi][ni][1];
                Cs[row + 8][col]     = acc[mi][ni][2];
                Cs[row + 8][col + 1] = acc[mi][ni][3];
            }
        }
    }
    __syncthreads();
    if (g == 1) {      // group 1 accumulates
#pragma unroll
        for (int mi = 0; mi < 2; mi++) {
            int row = wm * 32 + mi * 16 + (lane >> 2);
#pragma unroll
            for (int ni = 0; ni < 4; ni++) {
                int col = wn * 32 + ni * 8 + ((lane & 3) << 1);
                Cs[row][col]     += acc[mi][ni][0];
                Cs[row][col + 1] += acc[mi][ni][1];
                Cs[row + 8][col]     += acc[mi][ni][2];
                Cs[row + 8][col + 1] += acc[mi][ni][3];
            }
        }
    }
    __syncthreads();

    // -------- fused pointwise: thread -> 4 hidden units of batch row pm --------
    const int pm = tid & 127;
    const int pq = tid >> 7;             // quarter (0..3): units pq*4..pq*4+3
    const int pb = pm & 63;
    const int myLen = lens[pb];
    const float* xg = (const float*)(dsm) + pm * 64 + pq * 16;
    float* cptr = g_c + (size_t)pm * H_ + j0 + pq * 4;
    float4 c0 = *(const float4*)(cptr);
    float cst[4] = {c0.x, c0.y, c0.z, c0.w};

    __half hv4[4];
#pragma unroll
    for (int q = 0; q < 4; q++) {
        int jl = pq * 4 + q, nl = 4 * jl;
        float4 z  = *(const float4*)&Cs[pm][nl];
        float4 x4 = *(const float4*)(xg + 4 * q);
        float zi = z.x + x4.x + sBias[nl + 0];
        float zf = z.y + x4.y + sBias[nl + 1];
        float zg = z.z + x4.z + sBias[nl + 2];
        float zo = z.w + x4.w + sBias[nl + 3];
        float cv = sigm(zf) * cst[q] + sigm(zi) * tanh_f(zg);
        float hv = sigm(zo) * tanh_f(cv);
        cst[q] = cv;
        hv4[q] = __float2half(hv);
        if (pm < 64) {
            if (myLen == s + 1) out[(size_t)pb * (2 * H_) + j0 + jl] = hv;
        } else if (s == T_ - 1) {
            out[(size_t)pb * (2 * H_) + H_ + j0 + jl] = hv;
        }
    }
    *(float4*)(cptr) = make_float4(cst[0], cst[1], cst[2], cst[3]);
    *(uint2*)&g_h16[(size_t)pm * H_ + j0 + pq * 4] = *(uint2*)hv4;
}

// ---------------- launch ----------------
extern "C" void kernel_launch(void* const* d_in, const int* in_sizes, int n_in,
                              void* d_out, int out_size)
{
    (void)in_sizes; (void)n_in; (void)out_size;
    const int*   tokens = (const int*)  d_in[0];
    const int*   lens   = (const int*)  d_in[1];
    const float* embed  = (const float*)d_in[2];
    const float* W_ih   = (const float*)d_in[3];
    const float* W_hh   = (const float*)d_in[4];
    const float* b_ih   = (const float*)d_in[5];
    const float* b_hh   = (const float*)d_in[6];
    float* out = (float*)d_out;

    cudaFuncSetAttribute(lstm_step,
                         cudaFuncAttributeMaxDynamicSharedMemorySize, DYN_SMEM);

    void *pA, *pB, *pXg;
    cudaGetSymbolAddress(&pA, g_Acat);
    cudaGetSymbolAddress(&pB, g_Bcat);
    cudaGetSymbolAddress(&pXg, g_Xg);

    prep_all<<<NB_WHH + NB_WIH + NB_X + NB_MISC, 256>>>(
        tokens, embed, W_ih, W_hh, b_ih, b_hh);

    gemm_kernel<<<dim3(G4 / 64, TB / 128), 256>>>(
        (const __half*)pA, (const __half*)pB, (float*)pXg, KCAT, KCAT, G4, KCAT);

    for (int s = 0; s < T_; s++)
        lstm_step<<<NCTA, 512, DYN_SMEM>>>(s, lens, out);
}